// round 6
// baseline (speedup 1.0000x reference)
#include <cuda_runtime.h>
#include <cuda_bf16.h>

// Problem constants
#define BATCH 32
#define CCH   16     // channels
#define HID   128    // hidden
#define PCH   48     // perception channels = 3*C
#define HH    256
#define WW    256
#define TILE  128    // pixels per CTA (x-direction)

// smem strides (padded for bank-conflict-free MMA fragment access)
#define W1_S  136    // uint32 [48][136]   (tf32 w1^T: [k][n])
#define W2P_S 24     // uint32 [64][24]    (bf16x2-packed w2^T over k)
#define PS_S  52     // uint32 [128][52]   (tf32 perception [pixel][k])
#define HS_WS 68     // words  [128][68]   (bf16x2 h [pixel][hid/2])
#define UPD_S 18     // float  [128][18]

// smem byte offsets
#define OFF_W1  0
#define OFF_W2P 26112              // 48*136*4
#define OFF_B1  32256              // +64*24*4
#define OFF_B2  32768              // +128*4
#define OFF_PS  32832              // +16*4
#define OFF_HS  59456              // +128*52*4
#define OFF_UPD 94272              // +128*68*4 (bf16x2 words)
#define SMEM_BYTES 103488          // +128*18*4

__device__ __forceinline__ unsigned int f2tf32(float f) {
    unsigned int u;
    asm("cvt.rna.tf32.f32 %0, %1;" : "=r"(u) : "f"(f));
    return u;
}

__device__ __forceinline__ unsigned int pack_bf16(float lo, float hi) {
    unsigned short l = __bfloat16_as_ushort(__float2bfloat16(lo));
    unsigned short h = __bfloat16_as_ushort(__float2bfloat16(hi));
    return (unsigned int)l | ((unsigned int)h << 16);
}

extern __shared__ unsigned char smem_raw[];

__global__ void __launch_bounds__(256, 2)
nca_fused_kernel(const float* __restrict__ grid,
                 const float* __restrict__ noise,
                 const float* __restrict__ w1,
                 const float* __restrict__ b1,
                 const float* __restrict__ w2,
                 const float* __restrict__ b2,
                 float* __restrict__ out)
{
    unsigned int*  W1s  = (unsigned int*)(smem_raw + OFF_W1);
    unsigned int*  W2p  = (unsigned int*)(smem_raw + OFF_W2P);
    float*         B1s  = (float*)(smem_raw + OFF_B1);
    float*         B2s  = (float*)(smem_raw + OFF_B2);
    unsigned int*  Ps   = (unsigned int*)(smem_raw + OFF_PS);
    unsigned int*  Hs32 = (unsigned int*)(smem_raw + OFF_HS);
    float*         Upd  = (float*)(smem_raw + OFF_UPD);

    const int tid = threadIdx.x;
    const int b   = blockIdx.z;
    const int y   = blockIdx.y;
    const int x0  = blockIdx.x * TILE;

    // ---- Phase 0: stage weights/biases into smem ----
    // w1 global: [128 (n)][48 (k)] row-major -> W1s[k][n] as tf32
    for (int i = tid; i < HID * PCH; i += 256) {
        int n = i / PCH, k = i % PCH;
        W1s[k * W1_S + n] = f2tf32(w1[i]);
    }
    // w2 global: [16 (n)][128 (k)] -> W2p[k/2][n] packed bf16x2 (low = even k)
    for (int i = tid; i < CCH * (HID / 2); i += 256) {
        int n = i >> 6, k2 = i & 63;
        W2p[k2 * W2P_S + n] = pack_bf16(w2[n * HID + 2 * k2],
                                        w2[n * HID + 2 * k2 + 1]);
    }
    if (tid < HID) B1s[tid] = b1[tid];
    if (tid < CCH) B2s[tid] = b2[tid];

    // ---- Phase 1: perception -> Ps[pixel][48] (tf32) ----
    {
        const int ym = y - 1, yp = y + 1;
        const bool okm = (ym >= 0), okp = (yp < HH);
        #pragma unroll
        for (int i = 0; i < 8; i++) {
            int t = tid + 256 * i;          // 0..2047
            int c = t >> 7;                 // channel
            int x = t & 127;                // pixel in tile
            int gx = x0 + x;
            const float* base = grid + (((size_t)b * CCH + c) * HH) * WW;
            const float* r0 = base + (size_t)ym * WW;
            const float* r1 = base + (size_t)y * WW;
            const float* r2 = base + (size_t)yp * WW;
            const bool xm = (gx > 0), xp = (gx < WW - 1);

            float g00 = (okm && xm) ? __ldg(r0 + gx - 1) : 0.f;
            float g01 =  okm        ? __ldg(r0 + gx)     : 0.f;
            float g02 = (okm && xp) ? __ldg(r0 + gx + 1) : 0.f;
            float g10 =  xm         ? __ldg(r1 + gx - 1) : 0.f;
            float g11 =               __ldg(r1 + gx);
            float g12 =  xp         ? __ldg(r1 + gx + 1) : 0.f;
            float g20 = (okp && xm) ? __ldg(r2 + gx - 1) : 0.f;
            float g21 =  okp        ? __ldg(r2 + gx)     : 0.f;
            float g22 = (okp && xp) ? __ldg(r2 + gx + 1) : 0.f;

            // sobel_x exactly as written in the reference:
            // [[1,0,1],[2,0,-2],[1,0,-1]]/8 (correlation, no flip)
            float sx = 0.125f * (g00 + g02 + 2.f * g10 - 2.f * g12 + g20 - g22);
            float sy = 0.125f * (g00 + 2.f * g01 + g02 - g20 - 2.f * g21 - g22);

            Ps[x * PS_S + 3 * c + 0] = f2tf32(g11);
            Ps[x * PS_S + 3 * c + 1] = f2tf32(sx);
            Ps[x * PS_S + 3 * c + 2] = f2tf32(sy);
        }
    }
    __syncthreads();

    const int warp = tid >> 5;
    const int lane = tid & 31;
    const int gid  = lane >> 2;   // group id (row within fragment)
    const int tig  = lane & 3;    // thread in group
    const int m0   = warp * 16;   // this warp's 16 pixel rows

    // ---- Phase 2: GEMM1 (tf32): h[128px][128] = P[128x48] @ w1^T ----
    float acc[16][4];
    #pragma unroll
    for (int nt = 0; nt < 16; nt++)
        #pragma unroll
        for (int j = 0; j < 4; j++) acc[nt][j] = 0.f;

    #pragma unroll
    for (int kt = 0; kt < 6; kt++) {
        const int k0 = kt * 8;
        unsigned int a0 = Ps[(m0 + gid)     * PS_S + k0 + tig];
        unsigned int a1 = Ps[(m0 + gid + 8) * PS_S + k0 + tig];
        unsigned int a2 = Ps[(m0 + gid)     * PS_S + k0 + tig + 4];
        unsigned int a3 = Ps[(m0 + gid + 8) * PS_S + k0 + tig + 4];
        #pragma unroll
        for (int nt = 0; nt < 16; nt++) {
            const int n0 = nt * 8;
            unsigned int bb0 = W1s[(k0 + tig)     * W1_S + n0 + gid];
            unsigned int bb1 = W1s[(k0 + tig + 4) * W1_S + n0 + gid];
            asm volatile(
                "mma.sync.aligned.m16n8k8.row.col.f32.tf32.tf32.f32 "
                "{%0,%1,%2,%3}, {%4,%5,%6,%7}, {%8,%9}, {%0,%1,%2,%3};"
                : "+f"(acc[nt][0]), "+f"(acc[nt][1]),
                  "+f"(acc[nt][2]), "+f"(acc[nt][3])
                : "r"(a0), "r"(a1), "r"(a2), "r"(a3), "r"(bb0), "r"(bb1));
        }
    }

    // bias + ReLU -> Hs (bf16), each warp writes only its own 16 rows
    #pragma unroll
    for (int nt = 0; nt < 16; nt++) {
        const int col = nt * 8 + 2 * tig;
        const float bb0 = B1s[col], bb1 = B1s[col + 1];
        float v0 = fmaxf(acc[nt][0] + bb0, 0.f);
        float v1 = fmaxf(acc[nt][1] + bb1, 0.f);
        float v2 = fmaxf(acc[nt][2] + bb0, 0.f);
        float v3 = fmaxf(acc[nt][3] + bb1, 0.f);
        Hs32[(m0 + gid)     * HS_WS + nt * 4 + tig] = pack_bf16(v0, v1);
        Hs32[(m0 + gid + 8) * HS_WS + nt * 4 + tig] = pack_bf16(v2, v3);
    }
    __syncwarp();   // warp-private region: warp sync suffices

    // ---- Phase 3: GEMM2 (bf16): upd[128px][16] = h @ w2^T ----
    float f2a[2][4];
    #pragma unroll
    for (int nt = 0; nt < 2; nt++)
        #pragma unroll
        for (int j = 0; j < 4; j++) f2a[nt][j] = 0.f;

    #pragma unroll
    for (int kt = 0; kt < 8; kt++) {
        const int kw = kt * 8;  // word offset = k0/2, k0 = 16*kt
        unsigned int a0 = Hs32[(m0 + gid)     * HS_WS + kw + tig];
        unsigned int a1 = Hs32[(m0 + gid + 8) * HS_WS + kw + tig];
        unsigned int a2 = Hs32[(m0 + gid)     * HS_WS + kw + tig + 4];
        unsigned int a3 = Hs32[(m0 + gid + 8) * HS_WS + kw + tig + 4];
        #pragma unroll
        for (int nt = 0; nt < 2; nt++) {
            const int n0 = nt * 8;
            unsigned int bb0 = W2p[(kw + tig)     * W2P_S + n0 + gid];
            unsigned int bb1 = W2p[(kw + tig + 4) * W2P_S + n0 + gid];
            asm volatile(
                "mma.sync.aligned.m16n8k16.row.col.f32.bf16.bf16.f32 "
                "{%0,%1,%2,%3}, {%4,%5,%6,%7}, {%8,%9}, {%0,%1,%2,%3};"
                : "+f"(f2a[nt][0]), "+f"(f2a[nt][1]),
                  "+f"(f2a[nt][2]), "+f"(f2a[nt][3])
                : "r"(a0), "r"(a1), "r"(a2), "r"(a3), "r"(bb0), "r"(bb1));
        }
    }

    // bias + stage update to smem
    #pragma unroll
    for (int nt = 0; nt < 2; nt++) {
        const int col = nt * 8 + 2 * tig;
        const float bb0 = B2s[col], bb1 = B2s[col + 1];
        Upd[(m0 + gid)     * UPD_S + col]     = f2a[nt][0] + bb0;
        Upd[(m0 + gid)     * UPD_S + col + 1] = f2a[nt][1] + bb1;
        Upd[(m0 + gid + 8) * UPD_S + col]     = f2a[nt][2] + bb0;
        Upd[(m0 + gid + 8) * UPD_S + col + 1] = f2a[nt][3] + bb1;
    }
    __syncthreads();

    // ---- Phase 4: mask + residual + clip, coalesced stores ----
    const float* nrow = noise + ((size_t)b * HH + y) * WW + x0;
    #pragma unroll
    for (int i = 0; i < 8; i++) {
        int t = tid + 256 * i;
        int ch = t >> 7;
        int x  = t & 127;
        size_t gi = (((size_t)b * CCH + ch) * HH + y) * WW + x0 + x;
        float g  = __ldg(grid + gi);
        float mk = (__ldg(nrow + x) < 0.5f) ? 1.f : 0.f;
        float v  = g + Upd[x * UPD_S + ch] * mk;
        v = fminf(fmaxf(v, -2.f), 2.f);
        out[gi] = v;
    }
}

extern "C" void kernel_launch(void* const* d_in, const int* in_sizes, int n_in,
                              void* d_out, int out_size) {
    const float* grid  = (const float*)d_in[0];
    const float* noise = (const float*)d_in[1];
    const float* w1    = (const float*)d_in[2];
    const float* b1    = (const float*)d_in[3];
    const float* w2    = (const float*)d_in[4];
    const float* b2    = (const float*)d_in[5];
    float* out = (float*)d_out;

    static bool attr_set = false;   // one-time attribute; work per call is identical
    if (!attr_set) {
        cudaFuncSetAttribute(nca_fused_kernel,
                             cudaFuncAttributeMaxDynamicSharedMemorySize,
                             SMEM_BYTES);
        attr_set = true;
    }

    dim3 g(WW / TILE, HH, BATCH);   // (2, 256, 32)
    nca_fused_kernel<<<g, 256, SMEM_BYTES>>>(grid, noise, w1, b1, w2, b2, out);
}

// round 8
// speedup vs baseline: 2.1218x; 2.1218x over previous
#include <cuda_runtime.h>
#include <cuda_bf16.h>

// Problem constants
#define BATCH 32
#define CCH   16     // channels
#define HID   128    // hidden
#define PCH   48     // perception channels = 3*C
#define HH    256
#define WW    256
#define TILE  128    // pixels per CTA (x-direction)

// smem geometry
#define PS_S  52     // uint32 [128][52]  tf32 perception [pixel][k] (conflict-free frag reads)
#define UPD_S 18     // float  [128][18]  (aliases Ps region)

// smem word offsets
#define OFF_W1F 0        // 6144 words: W1 tf32 fragments  [kt=6][nt2=8][gid=8][tig=4][4]
#define OFF_W2F 6144     // 1024 words: W2 bf16x2 fragments [kt=8][gid=8][tig=4][4]
#define OFF_B1  7168     // 128 words
#define OFF_B2  7296     // 16 words
#define OFF_PS  7312     // 6656 words (Upd aliases this after compute)
#define SMEM_WORDS (OFF_PS + 128 * PS_S)          // 13968
#define SMEM_BYTES (SMEM_WORDS * 4)               // 55872

// Pre-converted weights (written by prep kernel each launch; no allocation)
__device__ unsigned int g_w1f[6144];
__device__ unsigned int g_w2f[1024];

__device__ __forceinline__ unsigned int f2tf32(float f) {
    unsigned int u;
    asm("cvt.rna.tf32.f32 %0, %1;" : "=r"(u) : "f"(f));
    return u;
}

__device__ __forceinline__ unsigned int pack_bf16(float lo, float hi) {
    unsigned short l = __bfloat16_as_ushort(__float2bfloat16(lo));
    unsigned short h = __bfloat16_as_ushort(__float2bfloat16(hi));
    return (unsigned int)l | ((unsigned int)h << 16);
}

// ---- prep: convert weights into MMA-fragment-native layouts, once per launch ----
__global__ void prep_weights(const float* __restrict__ w1,
                             const float* __restrict__ w2)
{
    int i = blockIdx.x * 256 + threadIdx.x;
    if (i < 6144) {
        // i = ((kt*8 + nt2)*8 + gid)*16 + tig*4 + j
        int j   = i & 3;
        int tig = (i >> 2) & 3;
        int gid = (i >> 4) & 7;
        int nt2 = (i >> 7) & 7;
        int kt  = i >> 10;                       // 0..5
        int k = kt * 8 + tig + ((j & 1) ? 4 : 0);
        int n = nt2 * 16 + gid + ((j & 2) ? 8 : 0);
        g_w1f[i] = f2tf32(w1[n * PCH + k]);      // w1 global: [128 n][48 k]
    }
    if (i < 1024) {
        // i = ((kt*8 + gid)*4 + tig)*4 + j
        int j   = i & 3;
        int tig = (i >> 2) & 3;
        int gid = (i >> 4) & 7;
        int kt  = i >> 7;                        // 0..7
        int kw = kt * 8 + tig + ((j & 1) ? 4 : 0);   // bf16x2 word row = k/2
        int n  = gid + ((j & 2) ? 8 : 0);
        g_w2f[i] = pack_bf16(w2[n * HID + 2 * kw], w2[n * HID + 2 * kw + 1]);
    }
}

extern __shared__ unsigned int smem_w[];

__global__ void __launch_bounds__(256, 3)
nca_fused_kernel(const float* __restrict__ grid,
                 const float* __restrict__ noise,
                 const float* __restrict__ b1,
                 const float* __restrict__ b2,
                 float* __restrict__ out)
{
    unsigned int* W1f = smem_w + OFF_W1F;
    unsigned int* W2f = smem_w + OFF_W2F;
    float*        B1s = (float*)(smem_w + OFF_B1);
    float*        B2s = (float*)(smem_w + OFF_B2);
    unsigned int* Ps  = smem_w + OFF_PS;
    float*        Upd = (float*)(smem_w + OFF_PS);   // aliases Ps (used after sync)

    const int tid = threadIdx.x;
    const int b   = blockIdx.z;
    const int y   = blockIdx.y;
    const int x0  = blockIdx.x * TILE;
    const int lane = tid & 31;

    // ---- Phase 0: copy pre-converted weights (coalesced uint4) ----
    {
        const uint4* s1 = (const uint4*)g_w1f;
        uint4*       d1 = (uint4*)W1f;
        #pragma unroll
        for (int i = 0; i < 6; i++) d1[tid + 256 * i] = s1[tid + 256 * i];
        ((uint4*)W2f)[tid] = ((const uint4*)g_w2f)[tid];
        if (tid < HID) B1s[tid] = b1[tid];
        if (tid < CCH) B2s[tid] = b2[tid];
    }

    // ---- Phase 1: perception -> Ps[pixel][48] (tf32), shuffle stencil ----
    {
        const int ym = y - 1, yp = y + 1;
        const bool okm = (ym >= 0), okp = (yp < HH);
        #pragma unroll
        for (int i = 0; i < 8; i++) {
            int t = tid + 256 * i;          // 0..2047
            int c = t >> 7;                 // channel
            int x = t & 127;                // pixel in tile
            int gx = x0 + x;
            const float* base = grid + (((size_t)b * CCH + c) * HH) * WW;
            const float* r0 = base + (size_t)ym * WW;
            const float* r1 = base + (size_t)y  * WW;
            const float* r2 = base + (size_t)yp * WW;

            float vm = okm ? __ldg(r0 + gx) : 0.f;
            float vc =       __ldg(r1 + gx);
            float vp = okp ? __ldg(r2 + gx) : 0.f;

            // warp lanes cover 32 consecutive x -> neighbors via shuffle
            float lm = __shfl_up_sync(0xffffffffu, vm, 1);
            float lc = __shfl_up_sync(0xffffffffu, vc, 1);
            float lp = __shfl_up_sync(0xffffffffu, vp, 1);
            float rm = __shfl_down_sync(0xffffffffu, vm, 1);
            float rc = __shfl_down_sync(0xffffffffu, vc, 1);
            float rp = __shfl_down_sync(0xffffffffu, vp, 1);
            if (lane == 0) {
                bool ok = (gx > 0);
                lm = (okm && ok) ? __ldg(r0 + gx - 1) : 0.f;
                lc =         ok  ? __ldg(r1 + gx - 1) : 0.f;
                lp = (okp && ok) ? __ldg(r2 + gx - 1) : 0.f;
            }
            if (lane == 31) {
                bool ok = (gx < WW - 1);
                rm = (okm && ok) ? __ldg(r0 + gx + 1) : 0.f;
                rc =         ok  ? __ldg(r1 + gx + 1) : 0.f;
                rp = (okp && ok) ? __ldg(r2 + gx + 1) : 0.f;
            }

            // sobel_x exactly as written in the reference (no flip):
            // [[1,0,1],[2,0,-2],[1,0,-1]]/8
            float sx = 0.125f * (lm + rm + 2.f * lc - 2.f * rc + lp - rp);
            float sy = 0.125f * (lm + 2.f * vm + rm - lp - 2.f * vp - rp);

            Ps[x * PS_S + 3 * c + 0] = f2tf32(vc);
            Ps[x * PS_S + 3 * c + 1] = f2tf32(sx);
            Ps[x * PS_S + 3 * c + 2] = f2tf32(sy);
        }
    }
    __syncthreads();

    const int warp = tid >> 5;
    const int gid  = lane >> 2;   // fragment row group
    const int tig  = lane & 3;    // thread in group
    const int m0   = warp * 16;   // this warp's 16 pixel rows

    // ---- Phase 2+3 fused: GEMM1 (tf32, N split in halves) feeding GEMM2 (bf16)
    //      via register-level fragment reuse (no h smem round trip) ----
    float f2a[2][4];
    #pragma unroll
    for (int nt = 0; nt < 2; nt++)
        #pragma unroll
        for (int j = 0; j < 4; j++) f2a[nt][j] = 0.f;

    #pragma unroll
    for (int half = 0; half < 2; half++) {
        float acc[8][4];
        #pragma unroll
        for (int nt = 0; nt < 8; nt++)
            #pragma unroll
            for (int j = 0; j < 4; j++) acc[nt][j] = 0.f;

        #pragma unroll
        for (int kt = 0; kt < 6; kt++) {
            const int k0 = kt * 8;
            unsigned int a0 = Ps[(m0 + gid)     * PS_S + k0 + tig];
            unsigned int a1 = Ps[(m0 + gid + 8) * PS_S + k0 + tig];
            unsigned int a2 = Ps[(m0 + gid)     * PS_S + k0 + tig + 4];
            unsigned int a3 = Ps[(m0 + gid + 8) * PS_S + k0 + tig + 4];
            #pragma unroll
            for (int q = 0; q < 4; q++) {
                const int nt2 = half * 4 + q;
                uint4 B = *(const uint4*)&W1f[(((kt * 8 + nt2) * 8 + gid) * 4 + tig) * 4];
                asm volatile(
                    "mma.sync.aligned.m16n8k8.row.col.f32.tf32.tf32.f32 "
                    "{%0,%1,%2,%3}, {%4,%5,%6,%7}, {%8,%9}, {%0,%1,%2,%3};"
                    : "+f"(acc[2*q][0]), "+f"(acc[2*q][1]),
                      "+f"(acc[2*q][2]), "+f"(acc[2*q][3])
                    : "r"(a0), "r"(a1), "r"(a2), "r"(a3), "r"(B.x), "r"(B.y));
                asm volatile(
                    "mma.sync.aligned.m16n8k8.row.col.f32.tf32.tf32.f32 "
                    "{%0,%1,%2,%3}, {%4,%5,%6,%7}, {%8,%9}, {%0,%1,%2,%3};"
                    : "+f"(acc[2*q+1][0]), "+f"(acc[2*q+1][1]),
                      "+f"(acc[2*q+1][2]), "+f"(acc[2*q+1][3])
                    : "r"(a0), "r"(a1), "r"(a2), "r"(a3), "r"(B.z), "r"(B.w));
            }
        }

        // bias + ReLU + pack -> GEMM2 A fragments directly from accumulators
        #pragma unroll
        for (int p = 0; p < 4; p++) {
            const int colbase = half * 64 + p * 16;
            const float b1a = B1s[colbase + 2 * tig];
            const float b1b = B1s[colbase + 2 * tig + 1];
            const float b1c = B1s[colbase + 8 + 2 * tig];
            const float b1d = B1s[colbase + 8 + 2 * tig + 1];

            unsigned int a0 = pack_bf16(fmaxf(acc[2*p][0] + b1a, 0.f),
                                        fmaxf(acc[2*p][1] + b1b, 0.f));
            unsigned int a1 = pack_bf16(fmaxf(acc[2*p][2] + b1a, 0.f),
                                        fmaxf(acc[2*p][3] + b1b, 0.f));
            unsigned int a2 = pack_bf16(fmaxf(acc[2*p+1][0] + b1c, 0.f),
                                        fmaxf(acc[2*p+1][1] + b1d, 0.f));
            unsigned int a3 = pack_bf16(fmaxf(acc[2*p+1][2] + b1c, 0.f),
                                        fmaxf(acc[2*p+1][3] + b1d, 0.f));

            const int ktg = half * 4 + p;    // GEMM2 k-tile
            uint4 B2 = *(const uint4*)&W2f[((ktg * 8 + gid) * 4 + tig) * 4];
            asm volatile(
                "mma.sync.aligned.m16n8k16.row.col.f32.bf16.bf16.f32 "
                "{%0,%1,%2,%3}, {%4,%5,%6,%7}, {%8,%9}, {%0,%1,%2,%3};"
                : "+f"(f2a[0][0]), "+f"(f2a[0][1]),
                  "+f"(f2a[0][2]), "+f"(f2a[0][3])
                : "r"(a0), "r"(a1), "r"(a2), "r"(a3), "r"(B2.x), "r"(B2.y));
            asm volatile(
                "mma.sync.aligned.m16n8k16.row.col.f32.bf16.bf16.f32 "
                "{%0,%1,%2,%3}, {%4,%5,%6,%7}, {%8,%9}, {%0,%1,%2,%3};"
                : "+f"(f2a[1][0]), "+f"(f2a[1][1]),
                  "+f"(f2a[1][2]), "+f"(f2a[1][3])
                : "r"(a0), "r"(a1), "r"(a2), "r"(a3), "r"(B2.z), "r"(B2.w));
        }
    }

    // all Ps reads done -> safe to overwrite region with Upd
    __syncthreads();

    #pragma unroll
    for (int nt = 0; nt < 2; nt++) {
        const int col = nt * 8 + 2 * tig;
        const float bb0 = B2s[col], bb1 = B2s[col + 1];
        Upd[(m0 + gid)     * UPD_S + col]     = f2a[nt][0] + bb0;
        Upd[(m0 + gid)     * UPD_S + col + 1] = f2a[nt][1] + bb1;
        Upd[(m0 + gid + 8) * UPD_S + col]     = f2a[nt][2] + bb0;
        Upd[(m0 + gid + 8) * UPD_S + col + 1] = f2a[nt][3] + bb1;
    }
    __syncthreads();

    // ---- Phase 4: mask + residual + clip, coalesced ----
    const float* nrow = noise + ((size_t)b * HH + y) * WW + x0;
    #pragma unroll
    for (int i = 0; i < 8; i++) {
        int t  = tid + 256 * i;
        int ch = t >> 7;
        int x  = t & 127;
        size_t gi = (((size_t)b * CCH + ch) * HH + y) * WW + x0 + x;
        float g  = __ldg(grid + gi);
        float mk = (__ldg(nrow + x) < 0.5f) ? 1.f : 0.f;
        float v  = g + Upd[x * UPD_S + ch] * mk;
        v = fminf(fmaxf(v, -2.f), 2.f);
        out[gi] = v;
    }
}

extern "C" void kernel_launch(void* const* d_in, const int* in_sizes, int n_in,
                              void* d_out, int out_size) {
    const float* grid  = (const float*)d_in[0];
    const float* noise = (const float*)d_in[1];
    const float* w1    = (const float*)d_in[2];
    const float* b1    = (const float*)d_in[3];
    const float* w2    = (const float*)d_in[4];
    const float* b2    = (const float*)d_in[5];
    float* out = (float*)d_out;

    static bool attr_set = false;   // one-time attribute; identical work per call
    if (!attr_set) {
        cudaFuncSetAttribute(nca_fused_kernel,
                             cudaFuncAttributeMaxDynamicSharedMemorySize,
                             SMEM_BYTES);
        attr_set = true;
    }

    prep_weights<<<24, 256>>>(w1, w2);   // 6144 threads; runs before main (same stream)

    dim3 g(WW / TILE, HH, BATCH);        // (2, 256, 32)
    nca_fused_kernel<<<g, 256, SMEM_BYTES>>>(grid, noise, b1, b2, out);
}

// round 11
// speedup vs baseline: 2.1282x; 1.0030x over previous
#include <cuda_runtime.h>
#include <cuda_bf16.h>

// Problem constants
#define BATCH 32
#define CCH   16     // channels
#define HID   128    // hidden
#define PCH   48     // perception channels = 3*C
#define HH    256
#define WW    256
#define TILE  128    // pixels per CTA (x-direction)

// smem geometry
#define PS_S  52     // uint32 [128][52]  tf32 perception [pixel][k] (conflict-free frag reads)
#define UPD_S 18     // float  [128][18]  (aliases Ps region)

// smem word offsets
#define OFF_W1F 0        // 6144 words: W1 tf32 fragments  [kt=6][nt2=8][gid=8][tig=4][4]
#define OFF_W2F 6144     // 1024 words: W2 bf16x2 fragments [kt=8][gid=8][tig=4][4]
#define OFF_B1  7168     // 128 words
#define OFF_B2  7296     // 16 words
#define OFF_PS  7312     // 6656 words (Upd aliases this after compute)
#define SMEM_WORDS (OFF_PS + 128 * PS_S)          // 13968
#define SMEM_BYTES (SMEM_WORDS * 4)               // 55872

// Pre-converted weights (written by prep kernel each launch; no allocation)
__device__ unsigned int g_w1f[6144];
__device__ unsigned int g_w2f[1024];

__device__ __forceinline__ unsigned int f2tf32(float f) {
    unsigned int u;
    asm("cvt.rna.tf32.f32 %0, %1;" : "=r"(u) : "f"(f));
    return u;
}

__device__ __forceinline__ unsigned int pack_bf16(float lo, float hi) {
    unsigned short l = __bfloat16_as_ushort(__float2bfloat16(lo));
    unsigned short h = __bfloat16_as_ushort(__float2bfloat16(hi));
    return (unsigned int)l | ((unsigned int)h << 16);
}

// ---- prep: convert weights into MMA-fragment-native layouts, once per launch ----
__global__ void prep_weights(const float* __restrict__ w1,
                             const float* __restrict__ w2)
{
    int i = blockIdx.x * 256 + threadIdx.x;
    if (i < 6144) {
        // i = ((kt*8 + nt2)*8 + gid)*16 + tig*4 + j
        int j   = i & 3;
        int tig = (i >> 2) & 3;
        int gid = (i >> 4) & 7;
        int nt2 = (i >> 7) & 7;
        int kt  = i >> 10;                       // 0..5
        int k = kt * 8 + tig + ((j & 1) ? 4 : 0);
        int n = nt2 * 16 + gid + ((j & 2) ? 8 : 0);
        g_w1f[i] = f2tf32(w1[n * PCH + k]);      // w1 global: [128 n][48 k]
    }
    if (i < 1024) {
        // i = ((kt*8 + gid)*4 + tig)*4 + j
        int j   = i & 3;
        int tig = (i >> 2) & 3;
        int gid = (i >> 4) & 7;
        int kt  = i >> 7;                        // 0..7
        int kw = kt * 8 + tig + ((j & 1) ? 4 : 0);   // bf16x2 word row = k/2
        int n  = gid + ((j & 2) ? 8 : 0);
        g_w2f[i] = pack_bf16(w2[n * HID + 2 * kw], w2[n * HID + 2 * kw + 1]);
    }
}

extern __shared__ unsigned int smem_w[];

__global__ void __launch_bounds__(256, 3)
nca_fused_kernel(const float* __restrict__ grid,
                 const float* __restrict__ noise,
                 const float* __restrict__ b1,
                 const float* __restrict__ b2,
                 float* __restrict__ out)
{
    unsigned int* W1f = smem_w + OFF_W1F;
    unsigned int* W2f = smem_w + OFF_W2F;
    float*        B1s = (float*)(smem_w + OFF_B1);
    float*        B2s = (float*)(smem_w + OFF_B2);
    unsigned int* Ps  = smem_w + OFF_PS;
    float*        Upd = (float*)(smem_w + OFF_PS);   // aliases Ps (used after sync)

    const int tid = threadIdx.x;
    const int b   = blockIdx.z;
    const int y   = blockIdx.y;
    const int x0  = blockIdx.x * TILE;
    const int lane = tid & 31;

    // ---- Phase 0: copy pre-converted weights (coalesced uint4) ----
    {
        const uint4* s1 = (const uint4*)g_w1f;
        uint4*       d1 = (uint4*)W1f;
        #pragma unroll
        for (int i = 0; i < 6; i++) d1[tid + 256 * i] = s1[tid + 256 * i];
        ((uint4*)W2f)[tid] = ((const uint4*)g_w2f)[tid];
        if (tid < HID) B1s[tid] = b1[tid];
        if (tid < CCH) B2s[tid] = b2[tid];
    }

    // ---- Phase 1: perception -> Ps[pixel][48] (tf32), shuffle stencil ----
    {
        const int ym = y - 1, yp = y + 1;
        const bool okm = (ym >= 0), okp = (yp < HH);
        #pragma unroll
        for (int i = 0; i < 8; i++) {
            int t = tid + 256 * i;          // 0..2047
            int c = t >> 7;                 // channel
            int x = t & 127;                // pixel in tile
            int gx = x0 + x;
            const float* base = grid + (((size_t)b * CCH + c) * HH) * WW;
            const float* r0 = base + (size_t)ym * WW;
            const float* r1 = base + (size_t)y  * WW;
            const float* r2 = base + (size_t)yp * WW;

            float vm = okm ? __ldg(r0 + gx) : 0.f;
            float vc =       __ldg(r1 + gx);
            float vp = okp ? __ldg(r2 + gx) : 0.f;

            // warp lanes cover 32 consecutive x -> neighbors via shuffle
            float lm = __shfl_up_sync(0xffffffffu, vm, 1);
            float lc = __shfl_up_sync(0xffffffffu, vc, 1);
            float lp = __shfl_up_sync(0xffffffffu, vp, 1);
            float rm = __shfl_down_sync(0xffffffffu, vm, 1);
            float rc = __shfl_down_sync(0xffffffffu, vc, 1);
            float rp = __shfl_down_sync(0xffffffffu, vp, 1);
            if (lane == 0) {
                bool ok = (gx > 0);
                lm = (okm && ok) ? __ldg(r0 + gx - 1) : 0.f;
                lc =         ok  ? __ldg(r1 + gx - 1) : 0.f;
                lp = (okp && ok) ? __ldg(r2 + gx - 1) : 0.f;
            }
            if (lane == 31) {
                bool ok = (gx < WW - 1);
                rm = (okm && ok) ? __ldg(r0 + gx + 1) : 0.f;
                rc =         ok  ? __ldg(r1 + gx + 1) : 0.f;
                rp = (okp && ok) ? __ldg(r2 + gx + 1) : 0.f;
            }

            // sobel_x exactly as written in the reference (no flip):
            // [[1,0,1],[2,0,-2],[1,0,-1]]/8
            float sx = 0.125f * (lm + rm + 2.f * lc - 2.f * rc + lp - rp);
            float sy = 0.125f * (lm + 2.f * vm + rm - lp - 2.f * vp - rp);

            Ps[x * PS_S + 3 * c + 0] = f2tf32(vc);
            Ps[x * PS_S + 3 * c + 1] = f2tf32(sx);
            Ps[x * PS_S + 3 * c + 2] = f2tf32(sy);
        }
    }
    __syncthreads();

    const int warp = tid >> 5;
    const int gid  = lane >> 2;   // fragment row group
    const int tig  = lane & 3;    // thread in group
    const int m0   = warp * 16;   // this warp's 16 pixel rows

    // ---- Phase 2+3 fused: GEMM1 (tf32, N split in halves) feeding GEMM2 (bf16)
    //      via register-level fragment reuse (no h smem round trip) ----
    float f2a[2][4];
    #pragma unroll
    for (int nt = 0; nt < 2; nt++)
        #pragma unroll
        for (int j = 0; j < 4; j++) f2a[nt][j] = 0.f;

    #pragma unroll
    for (int half = 0; half < 2; half++) {
        float acc[8][4];
        #pragma unroll
        for (int nt = 0; nt < 8; nt++)
            #pragma unroll
            for (int j = 0; j < 4; j++) acc[nt][j] = 0.f;

        #pragma unroll
        for (int kt = 0; kt < 6; kt++) {
            const int k0 = kt * 8;
            unsigned int a0 = Ps[(m0 + gid)     * PS_S + k0 + tig];
            unsigned int a1 = Ps[(m0 + gid + 8) * PS_S + k0 + tig];
            unsigned int a2 = Ps[(m0 + gid)     * PS_S + k0 + tig + 4];
            unsigned int a3 = Ps[(m0 + gid + 8) * PS_S + k0 + tig + 4];
            #pragma unroll
            for (int q = 0; q < 4; q++) {
                const int nt2 = half * 4 + q;
                uint4 B = *(const uint4*)&W1f[(((kt * 8 + nt2) * 8 + gid) * 4 + tig) * 4];
                asm volatile(
                    "mma.sync.aligned.m16n8k8.row.col.f32.tf32.tf32.f32 "
                    "{%0,%1,%2,%3}, {%4,%5,%6,%7}, {%8,%9}, {%0,%1,%2,%3};"
                    : "+f"(acc[2*q][0]), "+f"(acc[2*q][1]),
                      "+f"(acc[2*q][2]), "+f"(acc[2*q][3])
                    : "r"(a0), "r"(a1), "r"(a2), "r"(a3), "r"(B.x), "r"(B.y));
                asm volatile(
                    "mma.sync.aligned.m16n8k8.row.col.f32.tf32.tf32.f32 "
                    "{%0,%1,%2,%3}, {%4,%5,%6,%7}, {%8,%9}, {%0,%1,%2,%3};"
                    : "+f"(acc[2*q+1][0]), "+f"(acc[2*q+1][1]),
                      "+f"(acc[2*q+1][2]), "+f"(acc[2*q+1][3])
                    : "r"(a0), "r"(a1), "r"(a2), "r"(a3), "r"(B.z), "r"(B.w));
            }
        }

        // bias + ReLU + pack -> GEMM2 A fragments directly from accumulators
        #pragma unroll
        for (int p = 0; p < 4; p++) {
            const int colbase = half * 64 + p * 16;
            const float b1a = B1s[colbase + 2 * tig];
            const float b1b = B1s[colbase + 2 * tig + 1];
            const float b1c = B1s[colbase + 8 + 2 * tig];
            const float b1d = B1s[colbase + 8 + 2 * tig + 1];

            unsigned int a0 = pack_bf16(fmaxf(acc[2*p][0] + b1a, 0.f),
                                        fmaxf(acc[2*p][1] + b1b, 0.f));
            unsigned int a1 = pack_bf16(fmaxf(acc[2*p][2] + b1a, 0.f),
                                        fmaxf(acc[2*p][3] + b1b, 0.f));
            unsigned int a2 = pack_bf16(fmaxf(acc[2*p+1][0] + b1c, 0.f),
                                        fmaxf(acc[2*p+1][1] + b1d, 0.f));
            unsigned int a3 = pack_bf16(fmaxf(acc[2*p+1][2] + b1c, 0.f),
                                        fmaxf(acc[2*p+1][3] + b1d, 0.f));

            const int ktg = half * 4 + p;    // GEMM2 k-tile
            uint4 B2 = *(const uint4*)&W2f[((ktg * 8 + gid) * 4 + tig) * 4];
            asm volatile(
                "mma.sync.aligned.m16n8k16.row.col.f32.bf16.bf16.f32 "
                "{%0,%1,%2,%3}, {%4,%5,%6,%7}, {%8,%9}, {%0,%1,%2,%3};"
                : "+f"(f2a[0][0]), "+f"(f2a[0][1]),
                  "+f"(f2a[0][2]), "+f"(f2a[0][3])
                : "r"(a0), "r"(a1), "r"(a2), "r"(a3), "r"(B2.x), "r"(B2.y));
            asm volatile(
                "mma.sync.aligned.m16n8k16.row.col.f32.bf16.bf16.f32 "
                "{%0,%1,%2,%3}, {%4,%5,%6,%7}, {%8,%9}, {%0,%1,%2,%3};"
                : "+f"(f2a[1][0]), "+f"(f2a[1][1]),
                  "+f"(f2a[1][2]), "+f"(f2a[1][3])
                : "r"(a0), "r"(a1), "r"(a2), "r"(a3), "r"(B2.z), "r"(B2.w));
        }
    }

    // all Ps reads done -> safe to overwrite region with Upd
    __syncthreads();

    #pragma unroll
    for (int nt = 0; nt < 2; nt++) {
        const int col = nt * 8 + 2 * tig;
        const float bb0 = B2s[col], bb1 = B2s[col + 1];
        Upd[(m0 + gid)     * UPD_S + col]     = f2a[nt][0] + bb0;
        Upd[(m0 + gid)     * UPD_S + col + 1] = f2a[nt][1] + bb1;
        Upd[(m0 + gid + 8) * UPD_S + col]     = f2a[nt][2] + bb0;
        Upd[(m0 + gid + 8) * UPD_S + col + 1] = f2a[nt][3] + bb1;
    }
    __syncthreads();

    // ---- Phase 4: mask + residual + clip, coalesced ----
    const float* nrow = noise + ((size_t)b * HH + y) * WW + x0;
    #pragma unroll
    for (int i = 0; i < 8; i++) {
        int t  = tid + 256 * i;
        int ch = t >> 7;
        int x  = t & 127;
        size_t gi = (((size_t)b * CCH + ch) * HH + y) * WW + x0 + x;
        float g  = __ldg(grid + gi);
        float mk = (__ldg(nrow + x) < 0.5f) ? 1.f : 0.f;
        float v  = g + Upd[x * UPD_S + ch] * mk;
        v = fminf(fmaxf(v, -2.f), 2.f);
        out[gi] = v;
    }
}

extern "C" void kernel_launch(void* const* d_in, const int* in_sizes, int n_in,
                              void* d_out, int out_size) {
    const float* grid  = (const float*)d_in[0];
    const float* noise = (const float*)d_in[1];
    const float* w1    = (const float*)d_in[2];
    const float* b1    = (const float*)d_in[3];
    const float* w2    = (const float*)d_in[4];
    const float* b2    = (const float*)d_in[5];
    float* out = (float*)d_out;

    static bool attr_set = false;   // one-time attribute; identical work per call
    if (!attr_set) {
        cudaFuncSetAttribute(nca_fused_kernel,
                             cudaFuncAttributeMaxDynamicSharedMemorySize,
                             SMEM_BYTES);
        attr_set = true;
    }

    prep_weights<<<24, 256>>>(w1, w2);   // 6144 threads; runs before main (same stream)

    dim3 g(WW / TILE, HH, BATCH);        // (2, 256, 32)
    nca_fused_kernel<<<g, 256, SMEM_BYTES>>>(grid, noise, b1, b2, out);
}

// round 15
// speedup vs baseline: 2.6047x; 1.2239x over previous
#include <cuda_runtime.h>
#include <cuda_bf16.h>

// Problem constants
#define BATCH 32
#define CCH   16     // channels
#define HID   128    // hidden
#define PCH   48     // perception channels = 3*C
#define HH    256
#define WW    256
#define TILE  128    // pixels per CTA (x-direction)

// smem geometry
#define PS_SW 28     // words per pixel row: 24 data (48 bf16) + 4 pad; XOR-swizzled
#define UPD_S 19     // float [128][19] (odd stride -> conflict-free column reads)

// smem word offsets
#define OFF_WF 0         // 4096 words: W1 bf16 frags (3072) + W2 bf16 frags (1024)
#define OFF_B1 4096      // 128
#define OFF_B2 4224      // 16
#define OFF_NS 4240      // 128 (noise row)
#define OFF_PS 4368      // 128*28 = 3584 (Upd aliases this after compute)
#define SMEM_WORDS (OFF_PS + 128 * PS_SW)     // 7952
#define SMEM_BYTES (SMEM_WORDS * 4)           // 31808

// Pre-converted weights (written by prep kernel each launch; no allocation)
// layout W1 (words 0..3071):   i = (((kt*8+n2p)*8+gid)*4+tig)*4 + n2lo*2 + j
//   kt=0..2 (k16-tile), n2p=0..7 (n8-tile pair), n2=2*n2p+n2lo, j selects k-half
// layout W2 (words 3072..4095): r = ((kt*8+gid)*4+tig)*4 + j   (kt = k16-tile 0..7)
__device__ unsigned int g_wf[4096];

__device__ __forceinline__ unsigned int pack_bf16(float lo, float hi) {
    unsigned short l = __bfloat16_as_ushort(__float2bfloat16(lo));
    unsigned short h = __bfloat16_as_ushort(__float2bfloat16(hi));
    return (unsigned int)l | ((unsigned int)h << 16);
}

// ---- prep: convert weights into MMA-fragment-native bf16 layouts ----
__global__ void prep_weights(const float* __restrict__ w1,
                             const float* __restrict__ w2)
{
    int i = blockIdx.x * 256 + threadIdx.x;
    if (i < 3072) {
        int j    = i & 1;
        int n2lo = (i >> 1) & 1;
        int tig  = (i >> 2) & 3;
        int gid  = (i >> 4) & 7;
        int n2p  = (i >> 7) & 7;
        int kt   = i >> 10;                       // 0..2
        int n = (n2p * 2 + n2lo) * 8 + gid;       // hidden col 0..127
        int k = kt * 16 + 2 * tig + 8 * j;        // perception k 0..46 (even)
        g_wf[i] = pack_bf16(w1[n * PCH + k], w1[n * PCH + k + 1]);
    } else if (i < 4096) {
        int r   = i - 3072;
        int j   = r & 3;
        int tig = (r >> 2) & 3;
        int gid = (r >> 4) & 7;
        int kt  = r >> 7;                         // 0..7
        int kw  = kt * 8 + tig + ((j & 1) ? 4 : 0);   // bf16x2 word row = k/2
        int n   = gid + ((j & 2) ? 8 : 0);
        g_wf[i] = pack_bf16(w2[n * HID + 2 * kw], w2[n * HID + 2 * kw + 1]);
    }
}

extern __shared__ unsigned int smem_w[];

#define MMA_BF16(AC, A0, A1, A2, A3, B0, B1)                                  \
    asm volatile(                                                             \
        "mma.sync.aligned.m16n8k16.row.col.f32.bf16.bf16.f32 "                \
        "{%0,%1,%2,%3}, {%4,%5,%6,%7}, {%8,%9}, {%0,%1,%2,%3};"               \
        : "+f"((AC)[0]), "+f"((AC)[1]), "+f"((AC)[2]), "+f"((AC)[3])          \
        : "r"(A0), "r"(A1), "r"(A2), "r"(A3), "r"(B0), "r"(B1))

__global__ void __launch_bounds__(256, 3)
nca_fused_kernel(const float* __restrict__ grid,
                 const float* __restrict__ noise,
                 const float* __restrict__ b1,
                 const float* __restrict__ b2,
                 float* __restrict__ out)
{
    unsigned int* Wf  = smem_w + OFF_WF;
    float*        B1s = (float*)(smem_w + OFF_B1);
    float*        B2s = (float*)(smem_w + OFF_B2);
    float*        Ns  = (float*)(smem_w + OFF_NS);
    unsigned int* Ps  = smem_w + OFF_PS;
    float*        Upd = (float*)(smem_w + OFF_PS);   // aliases Ps (after sync)

    const int tid  = threadIdx.x;
    const int b    = blockIdx.z;
    const int y    = blockIdx.y;
    const int x0   = blockIdx.x * TILE;
    const int lane = tid & 31;

    // ---- Phase 0: stage weights (uint4), biases, noise row ----
    #pragma unroll
    for (int i = 0; i < 4; i++)
        ((uint4*)Wf)[tid + 256 * i] = ((const uint4*)g_wf)[tid + 256 * i];
    if (tid < HID)  B1s[tid] = b1[tid];
    if (tid < CCH)  B2s[tid] = b2[tid];
    if (tid < TILE) Ns[tid]  = noise[((size_t)b * HH + y) * WW + x0 + tid];

    // ---- Phase 1: perception -> Ps[pixel][48] (bf16, swizzled), keep centers ----
    float vcr[8];
    {
        const int ym = y - 1, yp = y + 1;
        const bool okm = (ym >= 0), okp = (yp < HH);
        #pragma unroll
        for (int i = 0; i < 8; i++) {
            int t = tid + 256 * i;          // 0..2047
            int c = t >> 7;                 // channel
            int x = t & 127;                // pixel in tile (lanes consecutive)
            int gx = x0 + x;
            const float* base = grid + (((size_t)b * CCH + c) * HH) * WW;
            const float* r0 = base + (size_t)ym * WW;
            const float* r1 = base + (size_t)y  * WW;
            const float* r2 = base + (size_t)yp * WW;

            float vm = okm ? __ldg(r0 + gx) : 0.f;
            float vc =       __ldg(r1 + gx);
            float vp = okp ? __ldg(r2 + gx) : 0.f;
            vcr[i] = vc;                    // reused in phase 4 (no grid re-read)

            float lm = __shfl_up_sync(0xffffffffu, vm, 1);
            float lc = __shfl_up_sync(0xffffffffu, vc, 1);
            float lp = __shfl_up_sync(0xffffffffu, vp, 1);
            float rm = __shfl_down_sync(0xffffffffu, vm, 1);
            float rc = __shfl_down_sync(0xffffffffu, vc, 1);
            float rp = __shfl_down_sync(0xffffffffu, vp, 1);
            if (lane == 0) {
                bool ok = (gx > 0);
                lm = (okm && ok) ? __ldg(r0 + gx - 1) : 0.f;
                lc =         ok  ? __ldg(r1 + gx - 1) : 0.f;
                lp = (okp && ok) ? __ldg(r2 + gx - 1) : 0.f;
            }
            if (lane == 31) {
                bool ok = (gx < WW - 1);
                rm = (okm && ok) ? __ldg(r0 + gx + 1) : 0.f;
                rc =         ok  ? __ldg(r1 + gx + 1) : 0.f;
                rp = (okp && ok) ? __ldg(r2 + gx + 1) : 0.f;
            }

            // sobel_x exactly as written in the reference (no flip):
            // [[1,0,1],[2,0,-2],[1,0,-1]]/8
            float sx = 0.125f * (lm + rm + 2.f * lc - 2.f * rc + lp - rp);
            float sy = 0.125f * (lm + 2.f * vm + rm - lp - 2.f * vp - rp);

            // bf16 stores, XOR-swizzled on word bits [0:2) by (x>>3)&3
            unsigned char* prow = (unsigned char*)Ps + x * (PS_SW * 4);
            int sw = ((x >> 3) & 3) << 2;
            *(__nv_bfloat16*)(prow + ((6 * c    ) ^ sw)) = __float2bfloat16(vc);
            *(__nv_bfloat16*)(prow + ((6 * c + 2) ^ sw)) = __float2bfloat16(sx);
            *(__nv_bfloat16*)(prow + ((6 * c + 4) ^ sw)) = __float2bfloat16(sy);
        }
    }
    __syncthreads();

    const int warp = tid >> 5;
    const int gid  = lane >> 2;
    const int tig  = lane & 3;
    const int m0   = warp * 16;
    const int s0   = (2 * warp) & 3;        // swizzle key for rows m0..m0+7
    const int s1   = (2 * warp + 1) & 3;    // rows m0+8..m0+15

    // ---- A fragments (bf16, K=48 = 3 k16-tiles), loaded ONCE for both halves ----
    unsigned int A[3][4];
    #pragma unroll
    for (int kt = 0; kt < 3; kt++) {
        A[kt][0] = Ps[(m0 + gid)     * PS_SW + ((kt * 8 + tig)     ^ s0)];
        A[kt][1] = Ps[(m0 + gid + 8) * PS_SW + ((kt * 8 + tig)     ^ s1)];
        A[kt][2] = Ps[(m0 + gid)     * PS_SW + ((kt * 8 + tig + 4) ^ s0)];
        A[kt][3] = Ps[(m0 + gid + 8) * PS_SW + ((kt * 8 + tig + 4) ^ s1)];
    }

    // ---- GEMM1 (bf16, N in halves) fused into GEMM2 (bf16) via registers ----
    float f2a[2][4];
    #pragma unroll
    for (int nt = 0; nt < 2; nt++)
        #pragma unroll
        for (int j = 0; j < 4; j++) f2a[nt][j] = 0.f;

    #pragma unroll
    for (int half = 0; half < 2; half++) {
        float acc[8][4];
        #pragma unroll
        for (int nt = 0; nt < 8; nt++)
            #pragma unroll
            for (int j = 0; j < 4; j++) acc[nt][j] = 0.f;

        #pragma unroll
        for (int kt = 0; kt < 3; kt++) {
            #pragma unroll
            for (int q = 0; q < 4; q++) {
                const int n2p = half * 4 + q;
                uint4 B = ((const uint4*)Wf)[((kt * 8 + n2p) * 8 + gid) * 4 + tig];
                MMA_BF16(acc[2*q],   A[kt][0], A[kt][1], A[kt][2], A[kt][3], B.x, B.y);
                MMA_BF16(acc[2*q+1], A[kt][0], A[kt][1], A[kt][2], A[kt][3], B.z, B.w);
            }
        }

        // bias + ReLU + pack -> GEMM2 A fragments straight from accumulators
        #pragma unroll
        for (int p = 0; p < 4; p++) {
            const int colbase = half * 64 + p * 16;
            const float b1a = B1s[colbase + 2 * tig];
            const float b1b = B1s[colbase + 2 * tig + 1];
            const float b1c = B1s[colbase + 8 + 2 * tig];
            const float b1d = B1s[colbase + 8 + 2 * tig + 1];

            unsigned int a0 = pack_bf16(fmaxf(acc[2*p][0] + b1a, 0.f),
                                        fmaxf(acc[2*p][1] + b1b, 0.f));
            unsigned int a1 = pack_bf16(fmaxf(acc[2*p][2] + b1a, 0.f),
                                        fmaxf(acc[2*p][3] + b1b, 0.f));
            unsigned int a2 = pack_bf16(fmaxf(acc[2*p+1][0] + b1c, 0.f),
                                        fmaxf(acc[2*p+1][1] + b1d, 0.f));
            unsigned int a3 = pack_bf16(fmaxf(acc[2*p+1][2] + b1c, 0.f),
                                        fmaxf(acc[2*p+1][3] + b1d, 0.f));

            const int ktg = half * 4 + p;    // GEMM2 k16-tile 0..7
            uint4 B2 = ((const uint4*)(Wf + 3072))[(ktg * 8 + gid) * 4 + tig];
            MMA_BF16(f2a[0], a0, a1, a2, a3, B2.x, B2.y);
            MMA_BF16(f2a[1], a0, a1, a2, a3, B2.z, B2.w);
        }
    }

    // all Ps reads done -> safe to overwrite region with Upd
    __syncthreads();

    #pragma unroll
    for (int nt = 0; nt < 2; nt++) {
        const int col = nt * 8 + 2 * tig;
        const float bb0 = B2s[col], bb1 = B2s[col + 1];
        Upd[(m0 + gid)     * UPD_S + col]     = f2a[nt][0] + bb0;
        Upd[(m0 + gid)     * UPD_S + col + 1] = f2a[nt][1] + bb1;
        Upd[(m0 + gid + 8) * UPD_S + col]     = f2a[nt][2] + bb0;
        Upd[(m0 + gid + 8) * UPD_S + col + 1] = f2a[nt][3] + bb1;
    }
    __syncthreads();

    // ---- Phase 4: mask + residual + clip (grid from registers, noise from smem) ----
    #pragma unroll
    for (int i = 0; i < 8; i++) {
        int t  = tid + 256 * i;
        int ch = t >> 7;
        int x  = t & 127;
        size_t gi = (((size_t)b * CCH + ch) * HH + y) * WW + x0 + x;
        float mk = (Ns[x] < 0.5f) ? 1.f : 0.f;
        float v  = vcr[i] + Upd[x * UPD_S + ch] * mk;
        v = fminf(fmaxf(v, -2.f), 2.f);
        out[gi] = v;
    }
}

extern "C" void kernel_launch(void* const* d_in, const int* in_sizes, int n_in,
                              void* d_out, int out_size) {
    const float* grid  = (const float*)d_in[0];
    const float* noise = (const float*)d_in[1];
    const float* w1    = (const float*)d_in[2];
    const float* b1    = (const float*)d_in[3];
    const float* w2    = (const float*)d_in[4];
    const float* b2    = (const float*)d_in[5];
    float* out = (float*)d_out;

    static bool attr_set = false;   // one-time attribute; identical work per call
    if (!attr_set) {
        cudaFuncSetAttribute(nca_fused_kernel,
                             cudaFuncAttributeMaxDynamicSharedMemorySize,
                             SMEM_BYTES);
        attr_set = true;
    }

    prep_weights<<<16, 256>>>(w1, w2);   // 4096 threads; same stream, runs first

    dim3 g(WW / TILE, HH, BATCH);        // (2, 256, 32)
    nca_fused_kernel<<<g, 256, SMEM_BYTES>>>(grid, noise, b1, b2, out);
}